// round 15
// baseline (speedup 1.0000x reference)
#include <cuda_runtime.h>
#include <cstdint>

#define N_NODES     200000
#define N_CLS       10
#define IDS_PER_CLS 20000
#define CENTER_BUDGET 2000
#define HOP_BUDGET  16384
#define CAND_CAP    16384
#define CCAP        4096
#define HGRID       148
#define TPB         1024
#define HNTH        (HGRID * TPB)
#define GS          16

struct Ctrl {
  unsigned cand_n;
  unsigned need2;
  unsigned thrT;
  unsigned take_all;
  int      is64;
};

__device__ Ctrl               g_ctrl;
__device__ unsigned           g_cnt[GS];
__device__ unsigned           g_flag[GS];
__device__ float              g_probs[N_NODES];
__device__ float              g_lp[N_NODES];     // logf(probs) cached by hop1
__device__ unsigned long long g_keys[N_NODES];
__device__ unsigned char      g_center[N_NODES];
__device__ unsigned char      g_retained[N_NODES];
__device__ unsigned char      g_nbr[N_NODES];
__device__ unsigned           g_hist[65536];
__device__ unsigned           g_chist[N_CLS * CCAP];
__device__ unsigned long long g_cand[CAND_CAP];
__device__ int                g_center_nodes[N_CLS * CENTER_BUDGET];

// ---------------------------------------------------------------------------
// threefry2x32 — matches JAX bit-for-bit (partitionable mode; validated)
// ---------------------------------------------------------------------------
__device__ __forceinline__ void tf2x32(unsigned k0, unsigned k1,
                                       unsigned x0, unsigned x1,
                                       unsigned &o0, unsigned &o1) {
  unsigned ks2 = k0 ^ k1 ^ 0x1BD11BDAu;
  x0 += k0; x1 += k1;
#define TFR(r) { x0 += x1; x1 = (x1 << (r)) | (x1 >> (32 - (r))); x1 ^= x0; }
  TFR(13) TFR(15) TFR(26) TFR(6)
  x0 += k1;  x1 += ks2 + 1u;
  TFR(17) TFR(29) TFR(16) TFR(24)
  x0 += ks2; x1 += k0 + 2u;
  TFR(13) TFR(15) TFR(26) TFR(6)
  x0 += k0;  x1 += k1 + 3u;
  TFR(17) TFR(29) TFR(16) TFR(24)
  x0 += k1;  x1 += ks2 + 4u;
  TFR(13) TFR(15) TFR(26) TFR(6)
  x0 += ks2; x1 += k0 + 5u;
#undef TFR
  o0 = x0; o1 = x1;
}
__device__ __forceinline__ unsigned pbits32(unsigned k0, unsigned k1, unsigned i) {
  unsigned o0, o1; tf2x32(k0, k1, 0u, i, o0, o1); return o0 ^ o1;
}
__device__ __forceinline__ unsigned long long pbits64(unsigned k0, unsigned k1, unsigned i) {
  unsigned o0, o1; tf2x32(k0, k1, 0u, i, o0, o1);
  return (((unsigned long long)o0) << 32) | o1;
}

// ---------------------------------------------------------------------------
// Replay-safe grid barrier (validated R9-R12).
// ---------------------------------------------------------------------------
__device__ __forceinline__ void gsync(int i) {
  __syncthreads();
  if (threadIdx.x == 0) {
    __threadfence();
    unsigned f0 = atomicAdd(&g_flag[i], 0u);
    __threadfence();
    if (atomicAdd(&g_cnt[i], 1u) == HGRID - 1u) {
      g_cnt[i] = 0u;
      __threadfence();
      atomicAdd(&g_flag[i], 1u);
    } else {
      while (atomicAdd(&g_flag[i], 0u) == f0) __nanosleep(64);
    }
    __threadfence();
  }
  __syncthreads();
}

extern __shared__ unsigned char s_raw[];

// ---------------------------------------------------------------------------
// Kernel 1: grid-wide zero (phase Z) | gsync | grid-wide center keygen
// (phase A) | gsync | per-class selection on blocks 0..9 (phase B).
// Phase B logic verbatim from R11/R12/R13 (counting-sort rank; validated).
// ---------------------------------------------------------------------------
__global__ __launch_bounds__(TPB, 1) void k_centers_start(const void* edge, long long E) {
  unsigned long long* skey  = (unsigned long long*)s_raw;          // 32KB
  unsigned*           sjdx  = (unsigned*)(s_raw + 32768);          // 16KB
  unsigned*           cur   = (unsigned*)(s_raw + 49152);          // 16KB
  unsigned*           ebase = (unsigned*)(s_raw + 65536);          // 16KB
  __shared__ unsigned part[1024];
  __shared__ int      s_bad, s_T;

  const int tid = threadIdx.x, bid = blockIdx.x;
  const int gt  = bid * TPB + tid;

  // ---- phase Z: zero state ----
  for (int i = gt; i < N_NODES; i += HNTH) {
    g_probs[i] = 0.f; g_center[i] = 0; g_retained[i] = 0; g_nbr[i] = 0;
  }
  for (int i = gt; i < 65536; i += HNTH) g_hist[i] = 0;
  for (int i = gt; i < N_CLS * CCAP; i += HNTH) g_chist[i] = 0;

  if (tid == 0) s_bad = 0;
  __syncthreads();
  {
    long long lim = (E < 128) ? E : 128;
    if (tid < 128 && (long long)tid < lim) {
      long long v = ((const long long*)edge)[tid];
      if (v < 0 || v >= N_NODES) atomicOr(&s_bad, 1);
    }
  }
  __syncthreads();
  const int is64 = s_bad ? 0 : 1;
  if (gt == 0) { g_ctrl.is64 = is64; g_ctrl.cand_n = 0; }
  gsync(0);                       // zeroing complete before any atomics

  // ---- phase A: center keygen + per-class histogram (grid-wide) ----
  unsigned kc0, kc1;
  tf2x32(0u, 42u, 0u, 0u, kc0, kc1);
  for (int m = gt; m < N_CLS * IDS_PER_CLS; m += HNTH) {
    int cls = m / IDS_PER_CLS;
    int j   = m - cls * IDS_PER_CLS;
    unsigned long long key; unsigned b;
    if (is64) {
      unsigned long long mant = pbits64(kc0, kc1, (unsigned)m) >> 12;  // u = mant*2^-52
      key = mant; b = (unsigned)(mant >> 40);
    } else {
      unsigned man = pbits32(kc0, kc1, (unsigned)m) >> 9;              // u = man*2^-23
      key = (((unsigned long long)man) << 32) | (unsigned)j;
      b = man >> 11;
    }
    g_keys[m] = key;
    atomicAdd(&g_chist[cls * CCAP + b], 1u);
  }
  gsync(1);

  // ---- phase B: per-class selection on blocks 0..9 ----
  if (bid >= N_CLS) return;
  const int c = bid, base = c * IDS_PER_CLS;

  for (int b = tid; b < CCAP; b += TPB) cur[b] = g_chist[c * CCAP + b];
  __syncthreads();

  unsigned c0 = cur[tid * 4 + 0], c1 = cur[tid * 4 + 1];
  unsigned c2 = cur[tid * 4 + 2], c3 = cur[tid * 4 + 3];
  unsigned mysum = c0 + c1 + c2 + c3;
  part[tid] = mysum; __syncthreads();
  for (int off = 1; off < TPB; off <<= 1) {
    unsigned v = part[tid];
    if (tid >= off) v += part[tid - off];
    __syncthreads(); part[tid] = v; __syncthreads();
  }
  unsigned P = part[tid];
  unsigned chunkbase = P - mysum;
  ebase[tid * 4 + 0] = chunkbase;
  ebase[tid * 4 + 1] = chunkbase + c0;
  ebase[tid * 4 + 2] = chunkbase + c0 + c1;
  ebase[tid * 4 + 3] = chunkbase + c0 + c1 + c2;
  if (P >= CENTER_BUDGET && chunkbase < CENTER_BUDGET) {
    unsigned acc = chunkbase; int T = tid * 4 + 3;
    acc += c0; if (acc >= CENTER_BUDGET) { T = tid * 4 + 0; goto gotT; }
    acc += c1; if (acc >= CENTER_BUDGET) { T = tid * 4 + 1; goto gotT; }
    acc += c2; if (acc >= CENTER_BUDGET) { T = tid * 4 + 2; goto gotT; }
  gotT:
    s_T = T;
  }
  __syncthreads();
  int T = s_T;

  for (int q = tid; q < CCAP; q += TPB) cur[q] = ebase[q];
  __syncthreads();
  for (int j = tid; j < IDS_PER_CLS; j += TPB) {
    int m = base + j;
    unsigned long long key = g_keys[m];
    unsigned b = is64 ? (unsigned)(key >> 40) : (unsigned)(key >> 43);
    if ((int)b <= T) {
      unsigned pos = atomicAdd(&cur[b], 1u);
      skey[pos] = key; sjdx[pos] = (unsigned)j;
    }
  }
  __syncthreads();
  int cnt = (int)cur[T];

  for (int p = tid; p < cnt; p += TPB) {
    unsigned long long k = skey[p];
    unsigned j = sjdx[p];
    unsigned b = is64 ? (unsigned)(k >> 40) : (unsigned)(k >> 43);
    unsigned st = ebase[b], en = cur[b];
    int rank = (int)st;
    for (unsigned i = st; i < en; i++) {
      unsigned long long ki = skey[i];
      unsigned ji = sjdx[i];
      rank += (ki < k) || (ki == k && ji < j);
    }
    if (rank < CENTER_BUDGET) {
      int node = base + (int)j;
      g_center_nodes[c * CENTER_BUDGET + rank] = node;
      g_center[node] = 1;
      g_retained[node] = 1;
    }
  }
}

// ---------------------------------------------------------------------------
// Kernel 2: fused edge pass (verbatim; measured ~95us standalone)
// ---------------------------------------------------------------------------
__global__ __launch_bounds__(256) void k_edges(const void* __restrict__ edge,
                                               const float* __restrict__ w, long long E) {
  long long base = ((long long)blockIdx.x * 256 + threadIdx.x) * 4;
  if (base >= E) return;
  int is64 = g_ctrl.is64;
  if (base + 3 < E) {
    int s[4], d[4];
    if (is64) {
      const ulonglong2* ps = (const ulonglong2*)((const long long*)edge + base);
      const ulonglong2* pd = (const ulonglong2*)((const long long*)edge + E + base);
      ulonglong2 s01 = ps[0], s23 = ps[1];
      ulonglong2 d01 = pd[0], d23 = pd[1];
      s[0]=(int)s01.x; s[1]=(int)s01.y; s[2]=(int)s23.x; s[3]=(int)s23.y;
      d[0]=(int)d01.x; d[1]=(int)d01.y; d[2]=(int)d23.x; d[3]=(int)d23.y;
    } else {
      const int4* ps = (const int4*)((const int*)edge + base);
      const int4* pd = (const int4*)((const int*)edge + E + base);
      int4 sv = ps[0], dv = pd[0];
      s[0]=sv.x; s[1]=sv.y; s[2]=sv.z; s[3]=sv.w;
      d[0]=dv.x; d[1]=dv.y; d[2]=dv.z; d[3]=dv.w;
    }
    float4 wv = *(const float4*)(w + base);
    atomicAdd(&g_probs[d[0]], wv.x);
    atomicAdd(&g_probs[d[1]], wv.y);
    atomicAdd(&g_probs[d[2]], wv.z);
    atomicAdd(&g_probs[d[3]], wv.w);
    unsigned char c0 = g_center[s[0]], c1 = g_center[s[1]];
    unsigned char c2 = g_center[s[2]], c3 = g_center[s[3]];
    if (c0) g_nbr[d[0]] = 1;
    if (c1) g_nbr[d[1]] = 1;
    if (c2) g_nbr[d[2]] = 1;
    if (c3) g_nbr[d[3]] = 1;
  } else {
    for (long long i = base; i < E; i++) {
      int s, d;
      if (is64) {
        const long long* p = (const long long*)edge;
        s = (int)p[i]; d = (int)p[E + i];
      } else {
        const int* p = (const int*)edge;
        s = p[i]; d = p[E + i];
      }
      atomicAdd(&g_probs[d], w[i]);
      if (g_center[s]) g_nbr[d] = 1;
    }
  }
}

// ---------------------------------------------------------------------------
// Kernel 3: persistent hops + output — R12-VERBATIM inline structure
// (h-loop, full per-hop build, g_hist reuse, inline thresh/refine).
// Only changes vs R12: gsync indices shifted to 2..9; hop2 reuses cached
// g_lp (bit-exact: same float value stored/reloaded).
// smem: skey u64[4096] 32KB | hist2 u32[4096] 16KB | part u32[1024] 4KB
// ---------------------------------------------------------------------------
__global__ __launch_bounds__(TPB, 1) void k_hops_out(float* __restrict__ out,
                                                     long long out_size) {
  unsigned long long* skey  = (unsigned long long*)s_raw;          // 32KB
  unsigned*           hist2 = (unsigned*)(s_raw + 32768);          // 16KB
  unsigned*           part  = (unsigned*)(s_raw + 49152);          // 4KB
  __shared__ unsigned s_scnt, s_need3;
  __shared__ int      s_T2;

  const int tid = threadIdx.x;
  const int bid = blockIdx.x;
  const int gt  = bid * TPB + tid;

  unsigned kA0, kA1, kB0, kB1;
  tf2x32(0u, 42u, 0u, 1u, kA0, kA1);   // k_h1
  tf2x32(0u, 42u, 0u, 2u, kB0, kB1);   // k_h2

  for (int h = 0; h < 2; h++) {
    unsigned kh0 = h ? kB0 : kA0, kh1 = h ? kB1 : kA1;

    // ---- build keys (candidate-skip; bit-exact gumbel, validated) ----
    for (int n = gt; n < N_NODES; n += HNTH) {
      unsigned long long kk = 0;
      if (g_nbr[n] && !g_retained[n]) {
        unsigned bits = pbits32(kh0, kh1, (unsigned)n);
        float ur = __uint_as_float((bits >> 9) | 0x3f800000u) - 1.0f;
        float u  = fmaxf(1.17549435e-38f, ur + 1.17549435e-38f);
        float g  = -logf(-logf(u));
        float lp;
        if (h == 0) { lp = logf(g_probs[n]); g_lp[n] = lp; }
        else        { lp = g_lp[n]; }
        float v  = lp + g;
        if (isfinite(v)) {
          unsigned b   = __float_as_uint(v);
          unsigned ord = b ^ ((b & 0x80000000u) ? 0xFFFFFFFFu : 0x80000000u);
          kk = (((unsigned long long)ord) << 32) | (0xFFFFFFFFu - (unsigned)n);
          atomicAdd(&g_hist[(unsigned)(kk >> 48)], 1u);
        }
      }
      g_keys[n] = kk;
    }
    gsync(2 + h * 4);

    // ---- threshold (block 0): suffix scan over 65536 digits ----
    if (bid == 0) {
      unsigned mysum = 0;
      #pragma unroll 8
      for (int b = tid * 64; b < tid * 64 + 64; b++) mysum += g_hist[b];
      part[tid] = mysum; __syncthreads();
      for (int off = 1; off < TPB; off <<= 1) {
        unsigned v = part[tid];
        if (tid + off < TPB) v += part[tid + off];
        __syncthreads(); part[tid] = v; __syncthreads();
      }
      unsigned total = part[0];
      unsigned need = (total < HOP_BUDGET) ? total : HOP_BUDGET;
      if (tid == 0 && need == 0) {
        g_ctrl.thrT = 0xFFFFFFFFu; g_ctrl.need2 = 0; g_ctrl.take_all = 0;
        g_ctrl.cand_n = 0;
      }
      if (need != 0) {
        unsigned S = part[tid];
        if (S >= need && S - mysum < need) {
          unsigned acc = S - mysum;
          for (int b = tid * 64 + 63; b >= tid * 64; b--) {
            unsigned hb = g_hist[b];
            if (acc + hb >= need) {
              g_ctrl.thrT = (unsigned)b;
              unsigned need2 = need - acc;
              g_ctrl.need2 = need2;
              g_ctrl.take_all = (need2 >= hb) ? 1u : 0u;
              g_ctrl.cand_n = 0;
              break;
            }
            acc += hb;
          }
        }
      }
    }
    gsync(3 + h * 4);

    // ---- scatter winners + collect boundary; re-zero hist for next hop ----
    {
      unsigned T = g_ctrl.thrT;
      unsigned take_all = g_ctrl.take_all;
      for (int n = gt; n < 65536; n += HNTH) g_hist[n] = 0;
      for (int n = gt; n < N_NODES; n += HNTH) {
        unsigned long long kk = g_keys[n];
        if (kk) {
          unsigned dg = (unsigned)(kk >> 48);
          if (dg > T) {
            g_retained[n] = 1;
          } else if (dg == T) {
            if (take_all) {
              g_retained[n] = 1;
            } else {
              unsigned pos = atomicAdd(&g_ctrl.cand_n, 1u);
              if (pos < CAND_CAP) g_cand[pos] = kk;
            }
          }
        }
      }
    }
    gsync(4 + h * 4);

    // ---- boundary refine (block 0): level-2 hist (bits 47:36) + rank ----
    if (bid == 0) {
      unsigned take_all = g_ctrl.take_all;
      unsigned need2 = g_ctrl.need2;
      if (!take_all && need2 != 0) {
        unsigned cn = g_ctrl.cand_n;
        int cnt = (int)((cn < CAND_CAP) ? cn : CAND_CAP);
        for (int b = tid; b < 4096; b += TPB) hist2[b] = 0;
        if (tid == 0) s_scnt = 0;
        __syncthreads();
        for (int i = tid; i < cnt; i += TPB)
          atomicAdd(&hist2[(unsigned)(g_cand[i] >> 36) & 0xFFFu], 1u);
        __syncthreads();

        unsigned mysum = 0;
        for (int b = tid * 4; b < tid * 4 + 4; b++) mysum += hist2[b];
        part[tid] = mysum; __syncthreads();
        for (int off = 1; off < TPB; off <<= 1) {
          unsigned v = part[tid];
          if (tid + off < TPB) v += part[tid + off];
          __syncthreads(); part[tid] = v; __syncthreads();
        }
        unsigned S = part[tid];
        if (S >= need2 && S - mysum < need2) {
          unsigned acc = S - mysum; int T2 = tid * 4; unsigned n3 = need2;
          for (int b = tid * 4 + 3; b >= tid * 4; b--) {
            unsigned hb = hist2[b];
            if (acc + hb >= need2) { T2 = b; n3 = need2 - acc; break; }
            acc += hb;
          }
          s_T2 = T2; s_need3 = n3;
        }
        __syncthreads();
        int T2 = s_T2;
        unsigned need3 = s_need3;

        for (int i = tid; i < cnt; i += TPB) {
          unsigned long long k = g_cand[i];
          int d2 = (int)((k >> 36) & 0xFFFu);
          if (d2 > T2) {
            g_retained[0xFFFFFFFFu - (unsigned)(k & 0xFFFFFFFFu)] = 1;
          } else if (d2 == T2) {
            unsigned p = atomicAdd(&s_scnt, 1u);
            if (p < 4096) skey[p] = k;
          }
        }
        __syncthreads();
        int c2 = (int)((s_scnt < 4096u) ? s_scnt : 4096u);
        for (int p = tid; p < c2; p += TPB) {
          unsigned long long myk = skey[p];
          int rank = 0;
          for (int i = 0; i < c2; i++) rank += (skey[i] > myk);
          if (rank < (int)need3)
            g_retained[0xFFFFFFFFu - (unsigned)(myk & 0xFFFFFFFFu)] = 1;
        }
      }
    }
    gsync(5 + h * 4);
  }

  // ---- output ----
  for (long long i = gt; i < out_size; i += HNTH) {
    float v;
    if (out_size == 420000) {
      if (i < 20000)        v = (float)g_center_nodes[i];
      else if (i < 220000)  v = g_retained[i - 20000] ? 1.f : 0.f;
      else                  v = g_retained[i - 220000] ? g_probs[i - 220000] : 0.f;
    } else if (out_size == 400000) {
      if (i < 200000)       v = g_retained[i] ? 1.f : 0.f;
      else                  v = g_retained[i - 200000] ? g_probs[i - 200000] : 0.f;
    } else if (out_size == 200000) {
      v = g_retained[i] ? g_probs[i] : 0.f;
    } else if (out_size == 20000) {
      v = (float)g_center_nodes[i];
    } else {
      v = 0.f;
    }
    out[i] = v;
  }
}

// ---------------------------------------------------------------------------
extern "C" void kernel_launch(void* const* d_in, const int* in_sizes, int n_in,
                              void* d_out, int out_size) {
  const void* edge = d_in[0];
  const float* w = (const float*)d_in[1];
  long long E = (long long)in_sizes[0] / 2;

  static int smem_set = 0;
  if (!smem_set) {
    cudaFuncSetAttribute(k_centers_start, cudaFuncAttributeMaxDynamicSharedMemorySize,
                         81920);
    cudaFuncSetAttribute(k_hops_out, cudaFuncAttributeMaxDynamicSharedMemorySize,
                         53248);
    smem_set = 1;
  }

  k_centers_start<<<HGRID, TPB, 81920>>>(edge, E);
  k_edges<<<(unsigned)((E + 1023) / 1024), 256>>>(edge, w, E);
  k_hops_out<<<HGRID, TPB, 53248>>>((float*)d_out, (long long)out_size);
}